// round 4
// baseline (speedup 1.0000x reference)
#include <cuda_runtime.h>
#include <cstdint>

#define T_TOK 8192
#define DIM   1024
#define FDIM  4096
#define NEXP  8
#define SLOTS (T_TOK*2)

// ---------------- device scratch (no allocs allowed) ----------------
__device__ float g_psum[NEXP];
__device__ int   g_cnt[NEXP];
__device__ int   g_fill[NEXP];
__device__ int   g_off[NEXP+1];
__device__ int   g_top[T_TOK*2];
__device__ float g_w[T_TOK*2];
__device__ int   g_tok_slot[T_TOK*2];
__device__ int   g_slot_tok[SLOTS];
__device__ float g_slot_gate[SLOTS];
__device__ float g_H[(size_t)SLOTS*FDIM];   // 256 MB SwiGLU intermediate
__device__ float g_Y[(size_t)SLOTS*DIM];    // 64 MB per-slot outputs (gated)

// ---------------- small helpers ----------------
__device__ __forceinline__ float to_tf32(float v){
    asm("cvt.rna.tf32.f32 %0, %1;" : "=f"(v) : "f"(v));
    return v;
}

__device__ __forceinline__ void mma8(float* c, const uint32_t* a, const uint32_t* b){
    asm volatile(
        "mma.sync.aligned.m16n8k8.row.col.f32.tf32.tf32.f32 "
        "{%0,%1,%2,%3},{%4,%5,%6,%7},{%8,%9},{%0,%1,%2,%3};"
        : "+f"(c[0]), "+f"(c[1]), "+f"(c[2]), "+f"(c[3])
        : "r"(a[0]), "r"(a[1]), "r"(a[2]), "r"(a[3]), "r"(b[0]), "r"(b[1]));
}

// ---------------- init ----------------
__global__ void init_kernel(){
    int i = threadIdx.x;
    if (i < NEXP){ g_psum[i] = 0.f; g_cnt[i] = 0; }
}

// ---------------- router: logits -> softmax -> top2 ----------------
__global__ void router_kernel(const float* __restrict__ x,
                              const float* __restrict__ Wg,
                              const float* __restrict__ bg){
    __shared__ float sps[NEXP];
    __shared__ int   scn[NEXP];
    if (threadIdx.x < NEXP){ sps[threadIdx.x] = 0.f; scn[threadIdx.x] = 0; }
    __syncthreads();

    const int lane = threadIdx.x & 31;
    const int t = (blockIdx.x * blockDim.x + threadIdx.x) >> 5;   // one warp per token

    float acc[NEXP];
#pragma unroll
    for (int e = 0; e < NEXP; e++) acc[e] = 0.f;

    const float* xr = x + (size_t)t * DIM;
    for (int d = lane; d < DIM; d += 32){
        float xv = xr[d];
        const float4* wr = (const float4*)(Wg + d * NEXP);
        float4 w0 = wr[0], w1 = wr[1];
        acc[0] = fmaf(xv, w0.x, acc[0]); acc[1] = fmaf(xv, w0.y, acc[1]);
        acc[2] = fmaf(xv, w0.z, acc[2]); acc[3] = fmaf(xv, w0.w, acc[3]);
        acc[4] = fmaf(xv, w1.x, acc[4]); acc[5] = fmaf(xv, w1.y, acc[5]);
        acc[6] = fmaf(xv, w1.z, acc[6]); acc[7] = fmaf(xv, w1.w, acc[7]);
    }
#pragma unroll
    for (int e = 0; e < NEXP; e++){
#pragma unroll
        for (int o = 16; o > 0; o >>= 1)
            acc[e] += __shfl_xor_sync(0xffffffffu, acc[e], o);
    }

    if (lane == 0){
        float p[NEXP];
        float mx = -1e30f;
#pragma unroll
        for (int e = 0; e < NEXP; e++){ p[e] = acc[e] + bg[e]; mx = fmaxf(mx, p[e]); }
        float s = 0.f;
#pragma unroll
        for (int e = 0; e < NEXP; e++){ p[e] = __expf(p[e] - mx); s += p[e]; }
        float inv = 1.f / s;
#pragma unroll
        for (int e = 0; e < NEXP; e++) p[e] *= inv;

        int e0 = 0;
#pragma unroll
        for (int e = 1; e < NEXP; e++) if (p[e] > p[e0]) e0 = e;
        int e1 = (e0 == 0) ? 1 : 0;
#pragma unroll
        for (int e = 0; e < NEXP; e++) if (e != e0 && p[e] > p[e1]) e1 = e;

        g_top[2*t]   = e0;  g_top[2*t+1] = e1;
        g_w[2*t]     = p[e0]; g_w[2*t+1]  = p[e1];
#pragma unroll
        for (int e = 0; e < NEXP; e++) atomicAdd(&sps[e], p[e]);
        atomicAdd(&scn[e0], 1);
        atomicAdd(&scn[e1], 1);
    }
    __syncthreads();
    if (threadIdx.x < NEXP){
        atomicAdd(&g_psum[threadIdx.x], sps[threadIdx.x]);
        atomicAdd(&g_cnt[threadIdx.x],  scn[threadIdx.x]);
    }
}

// ---------------- offsets + aux loss ----------------
__global__ void offsets_aux_kernel(float* __restrict__ out, int out_size){
    if (threadIdx.x == 0 && blockIdx.x == 0){
        int off = 0;
        float aux = 0.f;
        for (int e = 0; e < NEXP; e++){
            g_off[e] = off;
            off += g_cnt[e];
            aux += ((float)g_cnt[e] / (float)(T_TOK*2)) * (g_psum[e] / (float)T_TOK);
            g_fill[e] = 0;
        }
        g_off[NEXP] = off;
        if (out_size > T_TOK*DIM) out[T_TOK*DIM] = aux * (float)NEXP;
    }
}

// ---------------- scatter tokens into expert slot lists ----------------
__global__ void scatter_kernel(){
    int t = blockIdx.x * blockDim.x + threadIdx.x;
#pragma unroll
    for (int k = 0; k < 2; k++){
        int e = g_top[2*t+k];
        int pos = atomicAdd(&g_fill[e], 1);
        int slot = g_off[e] + pos;
        g_slot_tok[slot]  = t;
        g_slot_gate[slot] = g_w[2*t+k];
        g_tok_slot[2*t+k] = slot;
    }
}

// ---------------- grouped GEMM 1&3 fused + SwiGLU (2-stage smem pipeline) ----
// per block: 128 slot-rows x 64 F-cols of BOTH W1 and W3, K-loop over D
__global__ __launch_bounds__(256) void gemm13_kernel(const float* __restrict__ x,
                                                     const float* __restrict__ W1,
                                                     const float* __restrict__ W3){
    const int e   = blockIdx.z;
    const int off = g_off[e];
    const int cnt = g_off[e+1] - off;
    const int m0  = blockIdx.y * 128;
    if (m0 >= cnt) return;
    const int n0  = blockIdx.x * 64;

    __shared__ float sA [2][16][132];
    __shared__ float sB1[2][16][68];
    __shared__ float sB3[2][16][68];
    __shared__ int   sTok[128];

    const int tid = threadIdx.x;
    if (tid < 128){
        int m = m0 + tid; if (m >= cnt) m = cnt - 1;
        sTok[tid] = g_slot_tok[off + m];
    }
    __syncthreads();

    const int ar = tid >> 1;           // A row 0..127
    const int ak = (tid & 1) * 8;      // A k-offset 0 or 8
    const float* xp = x + (size_t)sTok[ar] * DIM + ak;
    const int br = tid >> 4;           // B row 0..15
    const int bc = (tid & 15) * 4;     // B col 0..60
    const float* w1p = W1 + ((size_t)e * DIM + br) * FDIM + n0 + bc;
    const float* w3p = W3 + ((size_t)e * DIM + br) * FDIM + n0 + bc;

    float acc1[2][4][4], acc3[2][4][4];
#pragma unroll
    for (int i = 0; i < 2; i++)
#pragma unroll
        for (int j = 0; j < 4; j++)
#pragma unroll
            for (int k = 0; k < 4; k++){ acc1[i][j][k] = 0.f; acc3[i][j][k] = 0.f; }

    float4 ra0, ra1, rb1, rb3;
    auto LOADG = [&](int kk){
        const float* xa = xp + kk * 16;
        ra0 = *(const float4*)(xa);
        ra1 = *(const float4*)(xa + 4);
        rb1 = *(const float4*)(w1p + (size_t)kk * 16 * FDIM);
        rb3 = *(const float4*)(w3p + (size_t)kk * 16 * FDIM);
    };
    auto STORES = [&](int st){
        sA[st][ak+0][ar] = to_tf32(ra0.x); sA[st][ak+1][ar] = to_tf32(ra0.y);
        sA[st][ak+2][ar] = to_tf32(ra0.z); sA[st][ak+3][ar] = to_tf32(ra0.w);
        sA[st][ak+4][ar] = to_tf32(ra1.x); sA[st][ak+5][ar] = to_tf32(ra1.y);
        sA[st][ak+6][ar] = to_tf32(ra1.z); sA[st][ak+7][ar] = to_tf32(ra1.w);
        float4 t1 = make_float4(to_tf32(rb1.x), to_tf32(rb1.y), to_tf32(rb1.z), to_tf32(rb1.w));
        float4 t3 = make_float4(to_tf32(rb3.x), to_tf32(rb3.y), to_tf32(rb3.z), to_tf32(rb3.w));
        *(float4*)&sB1[st][br][bc] = t1;
        *(float4*)&sB3[st][br][bc] = t3;
    };

    const int lane = tid & 31, wid = tid >> 5;
    const int wm = (wid & 3) * 32, wn = (wid >> 2) * 32;
    const int g = lane >> 2, tg = lane & 3;

    auto COMPUTE = [&](int st){
#pragma unroll
        for (int ks = 0; ks < 2; ks++){
            const int k0 = ks * 8;
            uint32_t af[2][4];
#pragma unroll
            for (int mi = 0; mi < 2; mi++){
                int r0 = wm + mi * 16;
                af[mi][0] = __float_as_uint(sA[st][k0+tg  ][r0+g  ]);
                af[mi][1] = __float_as_uint(sA[st][k0+tg  ][r0+8+g]);
                af[mi][2] = __float_as_uint(sA[st][k0+tg+4][r0+g  ]);
                af[mi][3] = __float_as_uint(sA[st][k0+tg+4][r0+8+g]);
            }
#pragma unroll
            for (int ni = 0; ni < 4; ni++){
                int nb = wn + ni * 8;
                uint32_t b1f[2] = { __float_as_uint(sB1[st][k0+tg][nb+g]), __float_as_uint(sB1[st][k0+tg+4][nb+g]) };
                uint32_t b3f[2] = { __float_as_uint(sB3[st][k0+tg][nb+g]), __float_as_uint(sB3[st][k0+tg+4][nb+g]) };
#pragma unroll
                for (int mi = 0; mi < 2; mi++){
                    mma8(acc1[mi][ni], af[mi], b1f);
                    mma8(acc3[mi][ni], af[mi], b3f);
                }
            }
        }
    };

    LOADG(0); STORES(0); __syncthreads();
    const int NK = DIM / 16;
    for (int kk = 0; kk < NK; kk++){
        const int cur = kk & 1;
        const bool nxt = (kk + 1) < NK;
        if (nxt) LOADG(kk + 1);
        COMPUTE(cur);
        if (nxt){ STORES(cur ^ 1); __syncthreads(); }
    }

    // epilogue: h = silu(a1) * a3  -> g_H
#pragma unroll
    for (int mi = 0; mi < 2; mi++){
#pragma unroll
        for (int ni = 0; ni < 4; ni++){
            int col = n0 + wn + ni * 8 + tg * 2;
#pragma unroll
            for (int h = 0; h < 2; h++){
                int r = wm + mi * 16 + g + h * 8;
                int m = m0 + r;
                if (m < cnt){
                    float v1a = acc1[mi][ni][h*2], v1b = acc1[mi][ni][h*2+1];
                    float v3a = acc3[mi][ni][h*2], v3b = acc3[mi][ni][h*2+1];
                    float2 o;
                    o.x = (v1a / (1.f + __expf(-v1a))) * v3a;
                    o.y = (v1b / (1.f + __expf(-v1b))) * v3b;
                    *(float2*)&g_H[(size_t)(off + m) * FDIM + col] = o;
                }
            }
        }
    }
}

// ---------------- grouped GEMM 2 (H @ W2) with gate epilogue (2-stage) ------
__global__ __launch_bounds__(256) void gemm2_kernel(const float* __restrict__ W2){
    const int e   = blockIdx.z;
    const int off = g_off[e];
    const int cnt = g_off[e+1] - off;
    const int m0  = blockIdx.y * 128;
    if (m0 >= cnt) return;
    const int n0  = blockIdx.x * 64;

    __shared__ float sA[2][16][132];
    __shared__ float sB[2][16][68];

    const int tid = threadIdx.x;
    const int ar = tid >> 1;
    const int ak = (tid & 1) * 8;
    int mrow = m0 + ar; if (mrow >= cnt) mrow = cnt - 1;
    const float* ap = g_H + (size_t)(off + mrow) * FDIM + ak;
    const int br = tid >> 4;
    const int bc = (tid & 15) * 4;
    const float* bp = W2 + ((size_t)e * FDIM + br) * DIM + n0 + bc;

    float acc[2][4][4];
#pragma unroll
    for (int i = 0; i < 2; i++)
#pragma unroll
        for (int j = 0; j < 4; j++)
#pragma unroll
            for (int k = 0; k < 4; k++) acc[i][j][k] = 0.f;

    float4 ra0, ra1, rb;
    auto LOADG = [&](int kk){
        const float* xa = ap + kk * 16;
        ra0 = *(const float4*)(xa);
        ra1 = *(const float4*)(xa + 4);
        rb  = *(const float4*)(bp + (size_t)kk * 16 * DIM);
    };
    auto STORES = [&](int st){
        sA[st][ak+0][ar] = to_tf32(ra0.x); sA[st][ak+1][ar] = to_tf32(ra0.y);
        sA[st][ak+2][ar] = to_tf32(ra0.z); sA[st][ak+3][ar] = to_tf32(ra0.w);
        sA[st][ak+4][ar] = to_tf32(ra1.x); sA[st][ak+5][ar] = to_tf32(ra1.y);
        sA[st][ak+6][ar] = to_tf32(ra1.z); sA[st][ak+7][ar] = to_tf32(ra1.w);
        float4 tb = make_float4(to_tf32(rb.x), to_tf32(rb.y), to_tf32(rb.z), to_tf32(rb.w));
        *(float4*)&sB[st][br][bc] = tb;
    };

    const int lane = tid & 31, wid = tid >> 5;
    const int wm = (wid & 3) * 32, wn = (wid >> 2) * 32;
    const int g = lane >> 2, tg = lane & 3;

    auto COMPUTE = [&](int st){
#pragma unroll
        for (int ks = 0; ks < 2; ks++){
            const int k0 = ks * 8;
            uint32_t af[2][4];
#pragma unroll
            for (int mi = 0; mi < 2; mi++){
                int r0 = wm + mi * 16;
                af[mi][0] = __float_as_uint(sA[st][k0+tg  ][r0+g  ]);
                af[mi][1] = __float_as_uint(sA[st][k0+tg  ][r0+8+g]);
                af[mi][2] = __float_as_uint(sA[st][k0+tg+4][r0+g  ]);
                af[mi][3] = __float_as_uint(sA[st][k0+tg+4][r0+8+g]);
            }
#pragma unroll
            for (int ni = 0; ni < 4; ni++){
                int nb = wn + ni * 8;
                uint32_t bf[2] = { __float_as_uint(sB[st][k0+tg][nb+g]), __float_as_uint(sB[st][k0+tg+4][nb+g]) };
#pragma unroll
                for (int mi = 0; mi < 2; mi++)
                    mma8(acc[mi][ni], af[mi], bf);
            }
        }
    };

    LOADG(0); STORES(0); __syncthreads();
    const int NK = FDIM / 16;
    for (int kk = 0; kk < NK; kk++){
        const int cur = kk & 1;
        const bool nxt = (kk + 1) < NK;
        if (nxt) LOADG(kk + 1);
        COMPUTE(cur);
        if (nxt){ STORES(cur ^ 1); __syncthreads(); }
    }

#pragma unroll
    for (int mi = 0; mi < 2; mi++){
#pragma unroll
        for (int h = 0; h < 2; h++){
            int r = wm + mi * 16 + g + h * 8;
            int m = m0 + r;
            if (m < cnt){
                float gate = g_slot_gate[off + m];
#pragma unroll
                for (int ni = 0; ni < 4; ni++){
                    int col = n0 + wn + ni * 8 + tg * 2;
                    float2 o;
                    o.x = acc[mi][ni][h*2]   * gate;
                    o.y = acc[mi][ni][h*2+1] * gate;
                    *(float2*)&g_Y[(size_t)(off + m) * DIM + col] = o;
                }
            }
        }
    }
}

// ---------------- combine two slots per token ----------------
__global__ void combine_kernel(float* __restrict__ out){
    int i = blockIdx.x * blockDim.x + threadIdx.x;    // over T*D/4 float4s
    int t = i >> 8;                                   // D/4 = 256
    int rem = i & 255;
    int s0 = g_tok_slot[2*t], s1 = g_tok_slot[2*t+1];
    const float4* Y = (const float4*)g_Y;
    float4 a = Y[(size_t)s0 * 256 + rem];
    float4 b = Y[(size_t)s1 * 256 + rem];
    float4 o = make_float4(a.x + b.x, a.y + b.y, a.z + b.z, a.w + b.w);
    ((float4*)out)[i] = o;
}

// ---------------- launch ----------------
extern "C" void kernel_launch(void* const* d_in, const int* in_sizes, int n_in,
                              void* d_out, int out_size){
    const float* x  = (const float*)d_in[0];
    const float* Wg = (const float*)d_in[1];
    const float* bg = (const float*)d_in[2];
    const float* W1 = (const float*)d_in[3];
    const float* W3 = (const float*)d_in[4];
    const float* W2 = (const float*)d_in[5];
    float* out = (float*)d_out;

    init_kernel<<<1, 32>>>();
    router_kernel<<<T_TOK/8, 256>>>(x, Wg, bg);
    offsets_aux_kernel<<<1, 1>>>(out, out_size);
    scatter_kernel<<<T_TOK/256, 256>>>();
    // grid.y covers worst-case expert occupancy (up to SLOTS rows in one expert)
    gemm13_kernel<<<dim3(FDIM/64, SLOTS/128, NEXP), 256>>>(x, W1, W3);
    gemm2_kernel<<<dim3(DIM/64, SLOTS/128, NEXP), 256>>>(W2);
    combine_kernel<<<(T_TOK*DIM/4)/256, 256>>>(out);
}

// round 5
// speedup vs baseline: 1.1333x; 1.1333x over previous
#include <cuda_runtime.h>
#include <cstdint>

#define T_TOK 8192
#define DIM   1024
#define FDIM  4096
#define NEXP  8
#define SLOTS (T_TOK*2)
#define SSTR  136   // smem row stride in floats; 136 mod 32 == 8 -> conflict-free frags

// ---------------- device scratch (no allocs allowed) ----------------
__device__ float g_psum[NEXP];
__device__ int   g_cnt[NEXP];
__device__ int   g_fill[NEXP];
__device__ int   g_off[NEXP+1];
__device__ int   g_top[T_TOK*2];
__device__ float g_w[T_TOK*2];
__device__ int   g_tok_slot[T_TOK*2];
__device__ int   g_slot_tok[SLOTS];
__device__ float g_slot_gate[SLOTS];
__device__ float g_H[(size_t)SLOTS*FDIM];   // 256 MB SwiGLU intermediate (tf32-rounded)
__device__ float g_Y[(size_t)SLOTS*DIM];    // 64 MB per-slot outputs (gated)

// ---------------- small helpers ----------------
__device__ __forceinline__ float to_tf32(float v){
    asm("cvt.rna.tf32.f32 %0, %1;" : "=f"(v) : "f"(v));
    return v;
}

__device__ __forceinline__ void mma8(float* c, const uint32_t* a, const uint32_t* b){
    asm volatile(
        "mma.sync.aligned.m16n8k8.row.col.f32.tf32.tf32.f32 "
        "{%0,%1,%2,%3},{%4,%5,%6,%7},{%8,%9},{%0,%1,%2,%3};"
        : "+f"(c[0]), "+f"(c[1]), "+f"(c[2]), "+f"(c[3])
        : "r"(a[0]), "r"(a[1]), "r"(a[2]), "r"(a[3]), "r"(b[0]), "r"(b[1]));
}

// ---------------- init ----------------
__global__ void init_kernel(){
    int i = threadIdx.x;
    if (i < NEXP){ g_psum[i] = 0.f; g_cnt[i] = 0; }
}

// ---------------- router: logits -> softmax -> top2 ----------------
__global__ void router_kernel(const float* __restrict__ x,
                              const float* __restrict__ Wg,
                              const float* __restrict__ bg){
    __shared__ float sps[NEXP];
    __shared__ int   scn[NEXP];
    if (threadIdx.x < NEXP){ sps[threadIdx.x] = 0.f; scn[threadIdx.x] = 0; }
    __syncthreads();

    const int lane = threadIdx.x & 31;
    const int t = (blockIdx.x * blockDim.x + threadIdx.x) >> 5;   // one warp per token

    float acc[NEXP];
#pragma unroll
    for (int e = 0; e < NEXP; e++) acc[e] = 0.f;

    const float* xr = x + (size_t)t * DIM;
    for (int d = lane; d < DIM; d += 32){
        float xv = xr[d];
        const float4* wr = (const float4*)(Wg + d * NEXP);
        float4 w0 = wr[0], w1 = wr[1];
        acc[0] = fmaf(xv, w0.x, acc[0]); acc[1] = fmaf(xv, w0.y, acc[1]);
        acc[2] = fmaf(xv, w0.z, acc[2]); acc[3] = fmaf(xv, w0.w, acc[3]);
        acc[4] = fmaf(xv, w1.x, acc[4]); acc[5] = fmaf(xv, w1.y, acc[5]);
        acc[6] = fmaf(xv, w1.z, acc[6]); acc[7] = fmaf(xv, w1.w, acc[7]);
    }
#pragma unroll
    for (int e = 0; e < NEXP; e++){
#pragma unroll
        for (int o = 16; o > 0; o >>= 1)
            acc[e] += __shfl_xor_sync(0xffffffffu, acc[e], o);
    }

    if (lane == 0){
        float p[NEXP];
        float mx = -1e30f;
#pragma unroll
        for (int e = 0; e < NEXP; e++){ p[e] = acc[e] + bg[e]; mx = fmaxf(mx, p[e]); }
        float s = 0.f;
#pragma unroll
        for (int e = 0; e < NEXP; e++){ p[e] = __expf(p[e] - mx); s += p[e]; }
        float inv = 1.f / s;
#pragma unroll
        for (int e = 0; e < NEXP; e++) p[e] *= inv;

        int e0 = 0;
#pragma unroll
        for (int e = 1; e < NEXP; e++) if (p[e] > p[e0]) e0 = e;
        int e1 = (e0 == 0) ? 1 : 0;
#pragma unroll
        for (int e = 0; e < NEXP; e++) if (e != e0 && p[e] > p[e1]) e1 = e;

        g_top[2*t]   = e0;  g_top[2*t+1] = e1;
        g_w[2*t]     = p[e0]; g_w[2*t+1]  = p[e1];
#pragma unroll
        for (int e = 0; e < NEXP; e++) atomicAdd(&sps[e], p[e]);
        atomicAdd(&scn[e0], 1);
        atomicAdd(&scn[e1], 1);
    }
    __syncthreads();
    if (threadIdx.x < NEXP){
        atomicAdd(&g_psum[threadIdx.x], sps[threadIdx.x]);
        atomicAdd(&g_cnt[threadIdx.x],  scn[threadIdx.x]);
    }
}

// ---------------- offsets + aux loss ----------------
__global__ void offsets_aux_kernel(float* __restrict__ out, int out_size){
    if (threadIdx.x == 0 && blockIdx.x == 0){
        int off = 0;
        float aux = 0.f;
        for (int e = 0; e < NEXP; e++){
            g_off[e] = off;
            off += g_cnt[e];
            aux += ((float)g_cnt[e] / (float)(T_TOK*2)) * (g_psum[e] / (float)T_TOK);
            g_fill[e] = 0;
        }
        g_off[NEXP] = off;
        if (out_size > T_TOK*DIM) out[T_TOK*DIM] = aux * (float)NEXP;
    }
}

// ---------------- scatter tokens into expert slot lists ----------------
__global__ void scatter_kernel(){
    int t = blockIdx.x * blockDim.x + threadIdx.x;
#pragma unroll
    for (int k = 0; k < 2; k++){
        int e = g_top[2*t+k];
        int pos = atomicAdd(&g_fill[e], 1);
        int slot = g_off[e] + pos;
        g_slot_tok[slot]  = t;
        g_slot_gate[slot] = g_w[2*t+k];
        g_tok_slot[2*t+k] = slot;
    }
}

// ---------------- grouped GEMM 1&3 fused + SwiGLU -------------------------
// 128 slot-rows x 128 F-cols of BOTH W1 and W3 per block, 512 threads,
// 16 warps as 4(M)x4(N), warp tile 32x32, 2-stage smem pipeline.
__global__ __launch_bounds__(512) void gemm13_kernel(const float* __restrict__ x,
                                                     const float* __restrict__ W1,
                                                     const float* __restrict__ W3){
    const int e   = blockIdx.z;
    const int off = g_off[e];
    const int cnt = g_off[e+1] - off;
    const int m0  = blockIdx.y * 128;
    if (m0 >= cnt) return;
    const int n0  = blockIdx.x * 128;

    extern __shared__ float dyn[];
    float (*sA )[16][SSTR] = (float(*)[16][SSTR])(dyn);
    float (*sB1)[16][SSTR] = (float(*)[16][SSTR])(dyn + 2*16*SSTR);
    float (*sB3)[16][SSTR] = (float(*)[16][SSTR])(dyn + 4*16*SSTR);
    __shared__ int sTok[128];

    const int tid = threadIdx.x;
    if (tid < 128){
        int m = m0 + tid; if (m >= cnt) m = cnt - 1;
        sTok[tid] = g_slot_tok[off + m];
    }
    __syncthreads();

    // A: thread loads one float4 of one row: row = tid&127, k-quarter = tid>>7
    const int arow = tid & 127;
    const int ak4  = (tid >> 7) * 4;
    const float* xp = x + (size_t)sTok[arow] * DIM + ak4;
    // B: thread loads one float4 of one k-row: k = tid>>5, col4 = (tid&31)*4
    const int bk  = tid >> 5;
    const int bc4 = (tid & 31) * 4;
    const float* w1p = W1 + ((size_t)e * DIM + bk) * FDIM + n0 + bc4;
    const float* w3p = W3 + ((size_t)e * DIM + bk) * FDIM + n0 + bc4;

    float acc1[2][4][4], acc3[2][4][4];
#pragma unroll
    for (int i = 0; i < 2; i++)
#pragma unroll
        for (int j = 0; j < 4; j++)
#pragma unroll
            for (int k = 0; k < 4; k++){ acc1[i][j][k] = 0.f; acc3[i][j][k] = 0.f; }

    float4 ra, rb1, rb3;
    auto LOADG = [&](int kk){
        ra  = *(const float4*)(xp + kk * 16);
        rb1 = *(const float4*)(w1p + (size_t)kk * 16 * FDIM);
        rb3 = *(const float4*)(w3p + (size_t)kk * 16 * FDIM);
    };
    auto STORES = [&](int st){
        sA[st][ak4+0][arow] = to_tf32(ra.x);
        sA[st][ak4+1][arow] = to_tf32(ra.y);
        sA[st][ak4+2][arow] = to_tf32(ra.z);
        sA[st][ak4+3][arow] = to_tf32(ra.w);
        *(float4*)&sB1[st][bk][bc4] = make_float4(to_tf32(rb1.x), to_tf32(rb1.y), to_tf32(rb1.z), to_tf32(rb1.w));
        *(float4*)&sB3[st][bk][bc4] = make_float4(to_tf32(rb3.x), to_tf32(rb3.y), to_tf32(rb3.z), to_tf32(rb3.w));
    };

    const int lane = tid & 31, wid = tid >> 5;
    const int wm = (wid & 3) * 32, wn = (wid >> 2) * 32;
    const int g = lane >> 2, tg = lane & 3;

    auto COMPUTE = [&](int st){
#pragma unroll
        for (int ks = 0; ks < 2; ks++){
            const int k0 = ks * 8;
            uint32_t af[2][4];
#pragma unroll
            for (int mi = 0; mi < 2; mi++){
                int r0 = wm + mi * 16;
                af[mi][0] = __float_as_uint(sA[st][k0+tg  ][r0+g  ]);
                af[mi][1] = __float_as_uint(sA[st][k0+tg  ][r0+8+g]);
                af[mi][2] = __float_as_uint(sA[st][k0+tg+4][r0+g  ]);
                af[mi][3] = __float_as_uint(sA[st][k0+tg+4][r0+8+g]);
            }
#pragma unroll
            for (int ni = 0; ni < 4; ni++){
                int nb = wn + ni * 8;
                uint32_t b1f[2] = { __float_as_uint(sB1[st][k0+tg][nb+g]), __float_as_uint(sB1[st][k0+tg+4][nb+g]) };
                uint32_t b3f[2] = { __float_as_uint(sB3[st][k0+tg][nb+g]), __float_as_uint(sB3[st][k0+tg+4][nb+g]) };
#pragma unroll
                for (int mi = 0; mi < 2; mi++){
                    mma8(acc1[mi][ni], af[mi], b1f);
                    mma8(acc3[mi][ni], af[mi], b3f);
                }
            }
        }
    };

    LOADG(0); STORES(0); __syncthreads();
    const int NK = DIM / 16;
    for (int kk = 0; kk < NK; kk++){
        const int cur = kk & 1;
        const bool nxt = (kk + 1) < NK;
        if (nxt) LOADG(kk + 1);
        COMPUTE(cur);
        if (nxt){ STORES(cur ^ 1); __syncthreads(); }
    }

    // epilogue: h = silu(a1) * a3, pre-rounded to tf32 -> g_H
#pragma unroll
    for (int mi = 0; mi < 2; mi++){
#pragma unroll
        for (int ni = 0; ni < 4; ni++){
            int col = n0 + wn + ni * 8 + tg * 2;
#pragma unroll
            for (int h = 0; h < 2; h++){
                int r = wm + mi * 16 + g + h * 8;
                int m = m0 + r;
                if (m < cnt){
                    float v1a = acc1[mi][ni][h*2], v1b = acc1[mi][ni][h*2+1];
                    float v3a = acc3[mi][ni][h*2], v3b = acc3[mi][ni][h*2+1];
                    float2 o;
                    o.x = to_tf32((v1a / (1.f + __expf(-v1a))) * v3a);
                    o.y = to_tf32((v1b / (1.f + __expf(-v1b))) * v3b);
                    *(float2*)&g_H[(size_t)(off + m) * FDIM + col] = o;
                }
            }
        }
    }
}

// ---------------- grouped GEMM 2 (H @ W2) with gate epilogue ----------------
// 128 slot-rows x 128 D-cols per block, 512 threads, warp tile 32x32.
__global__ __launch_bounds__(512) void gemm2_kernel(const float* __restrict__ W2){
    const int e   = blockIdx.z;
    const int off = g_off[e];
    const int cnt = g_off[e+1] - off;
    const int m0  = blockIdx.y * 128;
    if (m0 >= cnt) return;
    const int n0  = blockIdx.x * 128;

    __shared__ float sA[2][16][SSTR];
    __shared__ float sB[2][16][SSTR];

    const int tid = threadIdx.x;
    const int arow = tid & 127;
    const int ak4  = (tid >> 7) * 4;
    int mrow = m0 + arow; if (mrow >= cnt) mrow = cnt - 1;
    const float* ap = g_H + (size_t)(off + mrow) * FDIM + ak4;
    const int bk  = tid >> 5;
    const int bc4 = (tid & 31) * 4;
    const float* bp = W2 + ((size_t)e * FDIM + bk) * DIM + n0 + bc4;

    float acc[2][4][4];
#pragma unroll
    for (int i = 0; i < 2; i++)
#pragma unroll
        for (int j = 0; j < 4; j++)
#pragma unroll
            for (int k = 0; k < 4; k++) acc[i][j][k] = 0.f;

    float4 ra, rb;
    auto LOADG = [&](int kk){
        ra = *(const float4*)(ap + kk * 16);
        rb = *(const float4*)(bp + (size_t)kk * 16 * DIM);
    };
    auto STORES = [&](int st){
        // g_H is already tf32-rounded by gemm13's epilogue
        sA[st][ak4+0][arow] = ra.x;
        sA[st][ak4+1][arow] = ra.y;
        sA[st][ak4+2][arow] = ra.z;
        sA[st][ak4+3][arow] = ra.w;
        *(float4*)&sB[st][bk][bc4] = make_float4(to_tf32(rb.x), to_tf32(rb.y), to_tf32(rb.z), to_tf32(rb.w));
    };

    const int lane = tid & 31, wid = tid >> 5;
    const int wm = (wid & 3) * 32, wn = (wid >> 2) * 32;
    const int g = lane >> 2, tg = lane & 3;

    auto COMPUTE = [&](int st){
#pragma unroll
        for (int ks = 0; ks < 2; ks++){
            const int k0 = ks * 8;
            uint32_t af[2][4];
#pragma unroll
            for (int mi = 0; mi < 2; mi++){
                int r0 = wm + mi * 16;
                af[mi][0] = __float_as_uint(sA[st][k0+tg  ][r0+g  ]);
                af[mi][1] = __float_as_uint(sA[st][k0+tg  ][r0+8+g]);
                af[mi][2] = __float_as_uint(sA[st][k0+tg+4][r0+g  ]);
                af[mi][3] = __float_as_uint(sA[st][k0+tg+4][r0+8+g]);
            }
#pragma unroll
            for (int ni = 0; ni < 4; ni++){
                int nb = wn + ni * 8;
                uint32_t bf[2] = { __float_as_uint(sB[st][k0+tg][nb+g]), __float_as_uint(sB[st][k0+tg+4][nb+g]) };
#pragma unroll
                for (int mi = 0; mi < 2; mi++)
                    mma8(acc[mi][ni], af[mi], bf);
            }
        }
    };

    LOADG(0); STORES(0); __syncthreads();
    const int NK = FDIM / 16;
    for (int kk = 0; kk < NK; kk++){
        const int cur = kk & 1;
        const bool nxt = (kk + 1) < NK;
        if (nxt) LOADG(kk + 1);
        COMPUTE(cur);
        if (nxt){ STORES(cur ^ 1); __syncthreads(); }
    }

#pragma unroll
    for (int mi = 0; mi < 2; mi++){
#pragma unroll
        for (int h = 0; h < 2; h++){
            int r = wm + mi * 16 + g + h * 8;
            int m = m0 + r;
            if (m < cnt){
                float gate = g_slot_gate[off + m];
#pragma unroll
                for (int ni = 0; ni < 4; ni++){
                    int col = n0 + wn + ni * 8 + tg * 2;
                    float2 o;
                    o.x = acc[mi][ni][h*2]   * gate;
                    o.y = acc[mi][ni][h*2+1] * gate;
                    *(float2*)&g_Y[(size_t)(off + m) * DIM + col] = o;
                }
            }
        }
    }
}

// ---------------- combine two slots per token ----------------
__global__ void combine_kernel(float* __restrict__ out){
    int i = blockIdx.x * blockDim.x + threadIdx.x;    // over T*D/4 float4s
    int t = i >> 8;                                   // D/4 = 256
    int rem = i & 255;
    int s0 = g_tok_slot[2*t], s1 = g_tok_slot[2*t+1];
    const float4* Y = (const float4*)g_Y;
    float4 a = Y[(size_t)s0 * 256 + rem];
    float4 b = Y[(size_t)s1 * 256 + rem];
    float4 o = make_float4(a.x + b.x, a.y + b.y, a.z + b.z, a.w + b.w);
    ((float4*)out)[i] = o;
}

// ---------------- launch ----------------
extern "C" void kernel_launch(void* const* d_in, const int* in_sizes, int n_in,
                              void* d_out, int out_size){
    const float* x  = (const float*)d_in[0];
    const float* Wg = (const float*)d_in[1];
    const float* bg = (const float*)d_in[2];
    const float* W1 = (const float*)d_in[3];
    const float* W3 = (const float*)d_in[4];
    const float* W2 = (const float*)d_in[5];
    float* out = (float*)d_out;

    const int dynBytes = 6 * 16 * SSTR * 4;   // 52224 B: A + B1 + B3, 2 stages
    cudaFuncSetAttribute(gemm13_kernel, cudaFuncAttributeMaxDynamicSharedMemorySize, dynBytes);

    init_kernel<<<1, 32>>>();
    router_kernel<<<T_TOK/8, 256>>>(x, Wg, bg);
    offsets_aux_kernel<<<1, 1>>>(out, out_size);
    scatter_kernel<<<T_TOK/256, 256>>>();
    // grid.y covers worst-case expert occupancy (up to SLOTS rows in one expert)
    gemm13_kernel<<<dim3(FDIM/128, SLOTS/128, NEXP), 512, dynBytes>>>(x, W1, W3);
    gemm2_kernel<<<dim3(DIM/128, SLOTS/128, NEXP), 512>>>(W2);
    combine_kernel<<<(T_TOK*DIM/4)/256, 256>>>(out);
}

// round 8
// speedup vs baseline: 1.7671x; 1.5592x over previous
#include <cuda_runtime.h>
#include <cuda_fp16.h>
#include <cstdint>

#define T_TOK 8192
#define DIM   1024
#define FDIM  4096
#define NEXP  8
#define SLOTS (T_TOK*2)
#define PSTR  136            // [kpair][*] stride in uint32 words (128 + 8 pad)
#define STAGE (16*PSTR)      // words per stage per operand (16 kpairs)

// ---------------- device scratch (no allocs allowed) ----------------
__device__ float  g_psum[NEXP];
__device__ int    g_cnt[NEXP];
__device__ int    g_fill[NEXP];
__device__ int    g_off[NEXP+1];
__device__ int    g_top[T_TOK*2];
__device__ float  g_w[T_TOK*2];
__device__ int    g_tok_slot[T_TOK*2];
__device__ int    g_slot_tok[SLOTS];
__device__ float  g_slot_gate[SLOTS];
__device__ __half g_H[(size_t)SLOTS*FDIM];  // 128 MB SwiGLU intermediate (fp16)
__device__ float  g_Y[(size_t)SLOTS*DIM];   // 64 MB per-slot gated outputs

// ---------------- helpers ----------------
__device__ __forceinline__ uint32_t pack_h2(float lo, float hi){
    uint32_t r;
    asm("cvt.rn.f16x2.f32 %0, %1, %2;" : "=r"(r) : "f"(hi), "f"(lo));
    return r;
}

__device__ __forceinline__ void mma16(float* c, const uint32_t* a, const uint32_t* b){
    asm volatile(
        "mma.sync.aligned.m16n8k16.row.col.f32.f16.f16.f32 "
        "{%0,%1,%2,%3},{%4,%5,%6,%7},{%8,%9},{%0,%1,%2,%3};"
        : "+f"(c[0]), "+f"(c[1]), "+f"(c[2]), "+f"(c[3])
        : "r"(a[0]), "r"(a[1]), "r"(a[2]), "r"(a[3]), "r"(b[0]), "r"(b[1]));
}

// ---------------- init ----------------
__global__ void init_kernel(){
    int i = threadIdx.x;
    if (i < NEXP){ g_psum[i] = 0.f; g_cnt[i] = 0; }
}

// ---------------- router: logits -> softmax -> top2 ----------------
__global__ void router_kernel(const float* __restrict__ x,
                              const float* __restrict__ Wg,
                              const float* __restrict__ bg){
    __shared__ float sps[NEXP];
    __shared__ int   scn[NEXP];
    if (threadIdx.x < NEXP){ sps[threadIdx.x] = 0.f; scn[threadIdx.x] = 0; }
    __syncthreads();

    const int lane = threadIdx.x & 31;
    const int t = (blockIdx.x * blockDim.x + threadIdx.x) >> 5;

    float acc[NEXP];
#pragma unroll
    for (int e = 0; e < NEXP; e++) acc[e] = 0.f;

    const float* xr = x + (size_t)t * DIM;
    for (int d = lane; d < DIM; d += 32){
        float xv = xr[d];
        const float4* wr = (const float4*)(Wg + d * NEXP);
        float4 w0 = wr[0], w1 = wr[1];
        acc[0] = fmaf(xv, w0.x, acc[0]); acc[1] = fmaf(xv, w0.y, acc[1]);
        acc[2] = fmaf(xv, w0.z, acc[2]); acc[3] = fmaf(xv, w0.w, acc[3]);
        acc[4] = fmaf(xv, w1.x, acc[4]); acc[5] = fmaf(xv, w1.y, acc[5]);
        acc[6] = fmaf(xv, w1.z, acc[6]); acc[7] = fmaf(xv, w1.w, acc[7]);
    }
#pragma unroll
    for (int e = 0; e < NEXP; e++){
#pragma unroll
        for (int o = 16; o > 0; o >>= 1)
            acc[e] += __shfl_xor_sync(0xffffffffu, acc[e], o);
    }

    if (lane == 0){
        float p[NEXP];
        float mx = -1e30f;
#pragma unroll
        for (int e = 0; e < NEXP; e++){ p[e] = acc[e] + bg[e]; mx = fmaxf(mx, p[e]); }
        float s = 0.f;
#pragma unroll
        for (int e = 0; e < NEXP; e++){ p[e] = __expf(p[e] - mx); s += p[e]; }
        float inv = 1.f / s;
#pragma unroll
        for (int e = 0; e < NEXP; e++) p[e] *= inv;

        int e0 = 0;
#pragma unroll
        for (int e = 1; e < NEXP; e++) if (p[e] > p[e0]) e0 = e;
        int e1 = (e0 == 0) ? 1 : 0;
#pragma unroll
        for (int e = 0; e < NEXP; e++) if (e != e0 && p[e] > p[e1]) e1 = e;

        g_top[2*t]   = e0;  g_top[2*t+1] = e1;
        g_w[2*t]     = p[e0]; g_w[2*t+1]  = p[e1];
#pragma unroll
        for (int e = 0; e < NEXP; e++) atomicAdd(&sps[e], p[e]);
        atomicAdd(&scn[e0], 1);
        atomicAdd(&scn[e1], 1);
    }
    __syncthreads();
    if (threadIdx.x < NEXP){
        atomicAdd(&g_psum[threadIdx.x], sps[threadIdx.x]);
        atomicAdd(&g_cnt[threadIdx.x],  scn[threadIdx.x]);
    }
}

// ---------------- offsets + aux loss ----------------
__global__ void offsets_aux_kernel(float* __restrict__ out, int out_size){
    if (threadIdx.x == 0 && blockIdx.x == 0){
        int off = 0;
        float aux = 0.f;
        for (int e = 0; e < NEXP; e++){
            g_off[e] = off;
            off += g_cnt[e];
            aux += ((float)g_cnt[e] / (float)(T_TOK*2)) * (g_psum[e] / (float)T_TOK);
            g_fill[e] = 0;
        }
        g_off[NEXP] = off;
        if (out_size > T_TOK*DIM) out[T_TOK*DIM] = aux * (float)NEXP;
    }
}

// ---------------- scatter ----------------
__global__ void scatter_kernel(){
    int t = blockIdx.x * blockDim.x + threadIdx.x;
#pragma unroll
    for (int k = 0; k < 2; k++){
        int e = g_top[2*t+k];
        int pos = atomicAdd(&g_fill[e], 1);
        int slot = g_off[e] + pos;
        g_slot_tok[slot]  = t;
        g_slot_gate[slot] = g_w[2*t+k];
        g_tok_slot[2*t+k] = slot;
    }
}

// ---------------- grouped GEMM 1&3 fused + SwiGLU (fp16 operands) ----------
// 128 slot-rows x 128 F-cols of BOTH W1 and W3; 512 threads; warp tile 32x32;
// K-tile = 32 (two m16n8k16 steps); smem holds packed half2 pairs [kpair][row].
__global__ __launch_bounds__(512) void gemm13_kernel(const float* __restrict__ x,
                                                     const float* __restrict__ W1,
                                                     const float* __restrict__ W3){
    const int e   = blockIdx.z;
    const int off = g_off[e];
    const int cnt = g_off[e+1] - off;
    const int m0  = blockIdx.x * 128;
    if (m0 >= cnt) return;
    const int n0  = blockIdx.y * 128;

    extern __shared__ uint32_t dynu[];
    uint32_t* sA  = dynu;              // 2 stages x STAGE
    uint32_t* sB1 = dynu + 2*STAGE;
    uint32_t* sB3 = dynu + 4*STAGE;
    __shared__ int sTok[128];

    const int tid = threadIdx.x;
    if (tid < 128){
        int m = m0 + tid; if (m >= cnt) m = cnt - 1;
        sTok[tid] = g_slot_tok[off + m];
    }
    __syncthreads();

    // A: thread -> row (tid&127), k-quarter (tid>>7): 8 floats per stage
    const int arow = tid & 127;
    const int aq   = tid >> 7;                 // 0..3
    const float* xp = x + (size_t)sTok[arow] * DIM + aq * 8;
    // B: thread -> kpair (tid>>5), nseg (tid&31): rows k,k+1 of 4 n-cols
    const int kpi  = tid >> 5;                 // 0..15
    const int nseg = tid & 31;
    const float* w1p = W1 + ((size_t)e * DIM + kpi*2) * FDIM + n0 + nseg*4;
    const float* w3p = W3 + ((size_t)e * DIM + kpi*2) * FDIM + n0 + nseg*4;

    float acc1[2][4][4], acc3[2][4][4];
#pragma unroll
    for (int i = 0; i < 2; i++)
#pragma unroll
        for (int j = 0; j < 4; j++)
#pragma unroll
            for (int k = 0; k < 4; k++){ acc1[i][j][k] = 0.f; acc3[i][j][k] = 0.f; }

    float4 ra0, ra1, rb10, rb11, rb30, rb31;
    auto LOADG = [&](int kt){
        ra0  = *(const float4*)(xp + kt*32);
        ra1  = *(const float4*)(xp + kt*32 + 4);
        size_t bo = (size_t)kt * 32 * FDIM;
        rb10 = *(const float4*)(w1p + bo);
        rb11 = *(const float4*)(w1p + bo + FDIM);
        rb30 = *(const float4*)(w3p + bo);
        rb31 = *(const float4*)(w3p + bo + FDIM);
    };
    auto STORES = [&](int st){
        const int kb = aq * 4;
        uint32_t* a = sA + st*STAGE;
        a[(kb+0)*PSTR + arow] = pack_h2(ra0.x, ra0.y);
        a[(kb+1)*PSTR + arow] = pack_h2(ra0.z, ra0.w);
        a[(kb+2)*PSTR + arow] = pack_h2(ra1.x, ra1.y);
        a[(kb+3)*PSTR + arow] = pack_h2(ra1.z, ra1.w);
        uint4 q1, q3;
        q1.x = pack_h2(rb10.x, rb11.x); q1.y = pack_h2(rb10.y, rb11.y);
        q1.z = pack_h2(rb10.z, rb11.z); q1.w = pack_h2(rb10.w, rb11.w);
        q3.x = pack_h2(rb30.x, rb31.x); q3.y = pack_h2(rb30.y, rb31.y);
        q3.z = pack_h2(rb30.z, rb31.z); q3.w = pack_h2(rb30.w, rb31.w);
        *(uint4*)&sB1[st*STAGE + kpi*PSTR + nseg*4] = q1;
        *(uint4*)&sB3[st*STAGE + kpi*PSTR + nseg*4] = q3;
    };

    const int lane = tid & 31, wid = tid >> 5;
    const int wm = (wid & 3) * 32, wn = (wid >> 2) * 32;
    const int g = lane >> 2, tg = lane & 3;

    auto COMPUTE = [&](int st){
        const uint32_t* a  = sA  + st*STAGE;
        const uint32_t* b1 = sB1 + st*STAGE;
        const uint32_t* b3 = sB3 + st*STAGE;
#pragma unroll
        for (int ks = 0; ks < 2; ks++){
            const int kp0 = ks * 8;
            uint32_t af[2][4];
#pragma unroll
            for (int mi = 0; mi < 2; mi++){
                int r0 = wm + mi * 16;
                af[mi][0] = a[(kp0+tg  )*PSTR + r0+g  ];
                af[mi][1] = a[(kp0+tg  )*PSTR + r0+8+g];
                af[mi][2] = a[(kp0+4+tg)*PSTR + r0+g  ];
                af[mi][3] = a[(kp0+4+tg)*PSTR + r0+8+g];
            }
#pragma unroll
            for (int ni = 0; ni < 4; ni++){
                int nb = wn + ni * 8;
                uint32_t b1f[2] = { b1[(kp0+tg)*PSTR + nb+g], b1[(kp0+4+tg)*PSTR + nb+g] };
                uint32_t b3f[2] = { b3[(kp0+tg)*PSTR + nb+g], b3[(kp0+4+tg)*PSTR + nb+g] };
#pragma unroll
                for (int mi = 0; mi < 2; mi++){
                    mma16(acc1[mi][ni], af[mi], b1f);
                    mma16(acc3[mi][ni], af[mi], b3f);
                }
            }
        }
    };

    LOADG(0); STORES(0); __syncthreads();
    const int NK = DIM / 32;
    for (int kk = 0; kk < NK; kk++){
        const int cur = kk & 1;
        const bool nxt = (kk + 1) < NK;
        if (nxt) LOADG(kk + 1);
        COMPUTE(cur);
        if (nxt){ STORES(cur ^ 1); __syncthreads(); }
    }

    // epilogue: h = silu(a1)*a3 -> g_H (fp16, packed pairs)
#pragma unroll
    for (int mi = 0; mi < 2; mi++){
#pragma unroll
        for (int ni = 0; ni < 4; ni++){
            int col = n0 + wn + ni * 8 + tg * 2;
#pragma unroll
            for (int h = 0; h < 2; h++){
                int r = wm + mi * 16 + g + h * 8;
                int m = m0 + r;
                if (m < cnt){
                    float v1a = acc1[mi][ni][h*2], v1b = acc1[mi][ni][h*2+1];
                    float v3a = acc3[mi][ni][h*2], v3b = acc3[mi][ni][h*2+1];
                    float ox = (v1a / (1.f + __expf(-v1a))) * v3a;
                    float oy = (v1b / (1.f + __expf(-v1b))) * v3b;
                    *(uint32_t*)&g_H[(size_t)(off + m) * FDIM + col] = pack_h2(ox, oy);
                }
            }
        }
    }
}

// ---------------- grouped GEMM 2 (H @ W2) with gate epilogue (fp16) --------
__global__ __launch_bounds__(512) void gemm2_kernel(const float* __restrict__ W2){
    const int e   = blockIdx.z;
    const int off = g_off[e];
    const int cnt = g_off[e+1] - off;
    const int m0  = blockIdx.x * 128;
    if (m0 >= cnt) return;
    const int n0  = blockIdx.y * 128;

    __shared__ uint32_t sA[2*STAGE];
    __shared__ uint32_t sB[2*STAGE];

    const int tid = threadIdx.x;
    const int arow = tid & 127;
    const int aq   = tid >> 7;
    int mrow = m0 + arow; if (mrow >= cnt) mrow = cnt - 1;
    const __half* ap = g_H + (size_t)(off + mrow) * FDIM + aq * 8;
    const int kpi  = tid >> 5;
    const int nseg = tid & 31;
    const float* bp = W2 + ((size_t)e * FDIM + kpi*2) * DIM + n0 + nseg*4;

    float acc[2][4][4];
#pragma unroll
    for (int i = 0; i < 2; i++)
#pragma unroll
        for (int j = 0; j < 4; j++)
#pragma unroll
            for (int k = 0; k < 4; k++) acc[i][j][k] = 0.f;

    uint4 rah;
    float4 rb0, rb1;
    auto LOADG = [&](int kt){
        rah = *(const uint4*)(ap + kt*32);       // 8 halves, pairs along k
        size_t bo = (size_t)kt * 32 * DIM;
        rb0 = *(const float4*)(bp + bo);
        rb1 = *(const float4*)(bp + bo + DIM);
    };
    auto STORES = [&](int st){
        const int kb = aq * 4;
        uint32_t* a = sA + st*STAGE;
        a[(kb+0)*PSTR + arow] = rah.x;
        a[(kb+1)*PSTR + arow] = rah.y;
        a[(kb+2)*PSTR + arow] = rah.z;
        a[(kb+3)*PSTR + arow] = rah.w;
        uint4 q;
        q.x = pack_h2(rb0.x, rb1.x); q.y = pack_h2(rb0.y, rb1.y);
        q.z = pack_h2(rb0.z, rb1.z); q.w = pack_h2(rb0.w, rb1.w);
        *(uint4*)&sB[st*STAGE + kpi*PSTR + nseg*4] = q;
    };

    const int lane = tid & 31, wid = tid >> 5;
    const int wm = (wid & 3) * 32, wn = (wid >> 2) * 32;
    const int g = lane >> 2, tg = lane & 3;

    auto COMPUTE = [&](int st){
        const uint32_t* a = sA + st*STAGE;
        const uint32_t* b = sB + st*STAGE;
#pragma unroll
        for (int ks = 0; ks < 2; ks++){
            const int kp0 = ks * 8;
            uint32_t af[2][4];
#pragma unroll
            for (int mi = 0; mi < 2; mi++){
                int r0 = wm + mi * 16;
                af[mi][0] = a[(kp0+tg  )*PSTR + r0+g  ];
                af[mi][1] = a[(kp0+tg  )*PSTR + r0+8+g];
                af[mi][2] = a[(kp0+4+tg)*PSTR + r0+g  ];
                af[mi][3] = a[(kp0+4+tg)*PSTR + r0+8+g];
            }
#pragma unroll
            for (int ni = 0; ni < 4; ni++){
                int nb = wn + ni * 8;
                uint32_t bf[2] = { b[(kp0+tg)*PSTR + nb+g], b[(kp0+4+tg)*PSTR + nb+g] };
#pragma unroll
                for (int mi = 0; mi < 2; mi++)
                    mma16(acc[mi][ni], af[mi], bf);
            }
        }
    };

    LOADG(0); STORES(0); __syncthreads();
    const int NK = FDIM / 32;
    for (int kk = 0; kk < NK; kk++){
        const int cur = kk & 1;
        const bool nxt = (kk + 1) < NK;
        if (nxt) LOADG(kk + 1);
        COMPUTE(cur);
        if (nxt){ STORES(cur ^ 1); __syncthreads(); }
    }

#pragma unroll
    for (int mi = 0; mi < 2; mi++){
#pragma unroll
        for (int h = 0; h < 2; h++){
            int r = wm + mi * 16 + g + h * 8;
            int m = m0 + r;
            if (m < cnt){
                float gate = g_slot_gate[off + m];
#pragma unroll
                for (int ni = 0; ni < 4; ni++){
                    int col = n0 + wn + ni * 8 + tg * 2;
                    float2 o;
                    o.x = acc[mi][ni][h*2]   * gate;
                    o.y = acc[mi][ni][h*2+1] * gate;
                    *(float2*)&g_Y[(size_t)(off + m) * DIM + col] = o;
                }
            }
        }
    }
}

// ---------------- combine two slots per token ----------------
__global__ void combine_kernel(float* __restrict__ out){
    int i = blockIdx.x * blockDim.x + threadIdx.x;
    int t = i >> 8;
    int rem = i & 255;
    int s0 = g_tok_slot[2*t], s1 = g_tok_slot[2*t+1];
    const float4* Y = (const float4*)g_Y;
    float4 a = Y[(size_t)s0 * 256 + rem];
    float4 b = Y[(size_t)s1 * 256 + rem];
    ((float4*)out)[i] = make_float4(a.x + b.x, a.y + b.y, a.z + b.z, a.w + b.w);
}

// ---------------- launch ----------------
extern "C" void kernel_launch(void* const* d_in, const int* in_sizes, int n_in,
                              void* d_out, int out_size){
    const float* x  = (const float*)d_in[0];
    const float* Wg = (const float*)d_in[1];
    const float* bg = (const float*)d_in[2];
    const float* W1 = (const float*)d_in[3];
    const float* W3 = (const float*)d_in[4];
    const float* W2 = (const float*)d_in[5];
    float* out = (float*)d_out;

    const int dyn13 = 6 * STAGE * 4;   // A + B1 + B3, 2 stages = 52224 B
    cudaFuncSetAttribute(gemm13_kernel, cudaFuncAttributeMaxDynamicSharedMemorySize, dyn13);

    init_kernel<<<1, 32>>>();
    router_kernel<<<T_TOK/8, 256>>>(x, Wg, bg);
    offsets_aux_kernel<<<1, 1>>>(out, out_size);
    scatter_kernel<<<T_TOK/256, 256>>>();
    // grid.x = m-tiles (fastest) so co-resident CTAs share B tiles via L2
    gemm13_kernel<<<dim3(SLOTS/128, FDIM/128, NEXP), 512, dyn13>>>(x, W1, W3);
    gemm2_kernel<<<dim3(SLOTS/128, DIM/128, NEXP), 512>>>(W2);
    combine_kernel<<<(T_TOK*DIM/4)/256, 256>>>(out);
}

// round 9
// speedup vs baseline: 2.1717x; 1.2290x over previous
#include <cuda_runtime.h>
#include <cuda_fp16.h>
#include <cstdint>

#define T_TOK 8192
#define DIM   1024
#define FDIM  4096
#define NEXP  8
#define SLOTS (T_TOK*2)

#define ASTRW 20            // A smem row stride in words (16 kpairs + 4 pad) -> conflict-free
#define BSTRW 136           // B smem kpair-row stride in words (128 + 8 pad)
#define A_BYTES (128*ASTRW*4)     // 10240
#define B_BYTES (16*BSTRW*4)      // 8704
#define ST13 (A_BYTES + 2*B_BYTES)  // 27648 per stage (A,B1,B3)
#define ST2  (A_BYTES + B_BYTES)    // 18944 per stage (A,B)

// ---------------- device scratch (no allocs allowed) ----------------
__device__ float    g_psum[NEXP];
__device__ int      g_cnt[NEXP];
__device__ int      g_fill[NEXP];
__device__ int      g_off[NEXP+1];
__device__ int      g_top[T_TOK*2];
__device__ float    g_w[T_TOK*2];
__device__ int      g_tok_slot[T_TOK*2];
__device__ int      g_slot_tok[SLOTS];
__device__ float    g_slot_gate[SLOTS];
__device__ uint32_t g_xi [(size_t)T_TOK*(DIM/2)];        // 16 MB  x as k-pair half2
__device__ uint32_t g_w1i[(size_t)NEXP*(DIM/2)*FDIM];    // 64 MB  W1 pairs along d
__device__ uint32_t g_w3i[(size_t)NEXP*(DIM/2)*FDIM];    // 64 MB
__device__ uint32_t g_w2i[(size_t)NEXP*(FDIM/2)*DIM];    // 64 MB  W2 pairs along f
__device__ uint32_t g_Hu [(size_t)SLOTS*(FDIM/2)];       // 128 MB H fp16 pairs along f
__device__ float    g_Y  [(size_t)SLOTS*DIM];            // 64 MB

// ---------------- helpers ----------------
__device__ __forceinline__ uint32_t pack_h2(float lo, float hi){
    uint32_t r;
    asm("cvt.rn.f16x2.f32 %0, %1, %2;" : "=r"(r) : "f"(hi), "f"(lo));
    return r;
}
__device__ __forceinline__ uint32_t smem_u32(const void* p){
    uint32_t a;
    asm("{ .reg .u64 t; cvta.to.shared.u64 t, %1; cvt.u32.u64 %0, t; }" : "=r"(a) : "l"(p));
    return a;
}
__device__ __forceinline__ void cp16(uint32_t dst, const void* src){
    asm volatile("cp.async.ca.shared.global [%0], [%1], 16;" :: "r"(dst), "l"(src));
}
__device__ __forceinline__ void cp_commit(){ asm volatile("cp.async.commit_group;"); }
__device__ __forceinline__ void cp_wait1(){ asm volatile("cp.async.wait_group 1;"); }
__device__ __forceinline__ void cp_wait0(){ asm volatile("cp.async.wait_group 0;"); }

__device__ __forceinline__ void mma16(float* c, const uint32_t* a, const uint32_t* b){
    asm volatile(
        "mma.sync.aligned.m16n8k16.row.col.f32.f16.f16.f32 "
        "{%0,%1,%2,%3},{%4,%5,%6,%7},{%8,%9},{%0,%1,%2,%3};"
        : "+f"(c[0]), "+f"(c[1]), "+f"(c[2]), "+f"(c[3])
        : "r"(a[0]), "r"(a[1]), "r"(a[2]), "r"(a[3]), "r"(b[0]), "r"(b[1]));
}

// ---------------- init ----------------
__global__ void init_kernel(){
    int i = threadIdx.x;
    if (i < NEXP){ g_psum[i] = 0.f; g_cnt[i] = 0; }
}

// ---------------- prep: convert + pair-interleave to fp16 ----------------
__global__ void cvt_x_kernel(const float* __restrict__ x){
    int i = blockIdx.x * blockDim.x + threadIdx.x;        // over T_TOK*512
    float2 v = ((const float2*)x)[i];
    g_xi[i] = pack_h2(v.x, v.y);
}
__global__ void cvt_w13_kernel(const float* __restrict__ W1, const float* __restrict__ W3){
    int i = blockIdx.x * blockDim.x + threadIdx.x;        // over 8*512*4096
    int f  = i & (FDIM-1);
    int kp = (i >> 12) & (DIM/2 - 1);
    int e  = i >> 21;
    size_t s = ((size_t)e*DIM + 2*kp)*FDIM + f;
    g_w1i[i] = pack_h2(W1[s], W1[s + FDIM]);
    g_w3i[i] = pack_h2(W3[s], W3[s + FDIM]);
}
__global__ void cvt_w2_kernel(const float* __restrict__ W2){
    int i = blockIdx.x * blockDim.x + threadIdx.x;        // over 8*2048*1024
    int d  = i & (DIM-1);
    int fp = (i >> 10) & (FDIM/2 - 1);
    int e  = i >> 21;
    size_t s = ((size_t)e*FDIM + 2*fp)*DIM + d;
    g_w2i[i] = pack_h2(W2[s], W2[s + DIM]);
}

// ---------------- router ----------------
__global__ void router_kernel(const float* __restrict__ x,
                              const float* __restrict__ Wg,
                              const float* __restrict__ bg){
    __shared__ float sps[NEXP];
    __shared__ int   scn[NEXP];
    if (threadIdx.x < NEXP){ sps[threadIdx.x] = 0.f; scn[threadIdx.x] = 0; }
    __syncthreads();

    const int lane = threadIdx.x & 31;
    const int t = (blockIdx.x * blockDim.x + threadIdx.x) >> 5;

    float acc[NEXP];
#pragma unroll
    for (int e = 0; e < NEXP; e++) acc[e] = 0.f;

    const float* xr = x + (size_t)t * DIM;
    for (int d = lane; d < DIM; d += 32){
        float xv = xr[d];
        const float4* wr = (const float4*)(Wg + d * NEXP);
        float4 w0 = wr[0], w1 = wr[1];
        acc[0] = fmaf(xv, w0.x, acc[0]); acc[1] = fmaf(xv, w0.y, acc[1]);
        acc[2] = fmaf(xv, w0.z, acc[2]); acc[3] = fmaf(xv, w0.w, acc[3]);
        acc[4] = fmaf(xv, w1.x, acc[4]); acc[5] = fmaf(xv, w1.y, acc[5]);
        acc[6] = fmaf(xv, w1.z, acc[6]); acc[7] = fmaf(xv, w1.w, acc[7]);
    }
#pragma unroll
    for (int e = 0; e < NEXP; e++){
#pragma unroll
        for (int o = 16; o > 0; o >>= 1)
            acc[e] += __shfl_xor_sync(0xffffffffu, acc[e], o);
    }

    if (lane == 0){
        float p[NEXP];
        float mx = -1e30f;
#pragma unroll
        for (int e = 0; e < NEXP; e++){ p[e] = acc[e] + bg[e]; mx = fmaxf(mx, p[e]); }
        float s = 0.f;
#pragma unroll
        for (int e = 0; e < NEXP; e++){ p[e] = __expf(p[e] - mx); s += p[e]; }
        float inv = 1.f / s;
#pragma unroll
        for (int e = 0; e < NEXP; e++) p[e] *= inv;

        int e0 = 0;
#pragma unroll
        for (int e = 1; e < NEXP; e++) if (p[e] > p[e0]) e0 = e;
        int e1 = (e0 == 0) ? 1 : 0;
#pragma unroll
        for (int e = 0; e < NEXP; e++) if (e != e0 && p[e] > p[e1]) e1 = e;

        g_top[2*t]   = e0;  g_top[2*t+1] = e1;
        g_w[2*t]     = p[e0]; g_w[2*t+1]  = p[e1];
#pragma unroll
        for (int e = 0; e < NEXP; e++) atomicAdd(&sps[e], p[e]);
        atomicAdd(&scn[e0], 1);
        atomicAdd(&scn[e1], 1);
    }
    __syncthreads();
    if (threadIdx.x < NEXP){
        atomicAdd(&g_psum[threadIdx.x], sps[threadIdx.x]);
        atomicAdd(&g_cnt[threadIdx.x],  scn[threadIdx.x]);
    }
}

// ---------------- offsets + aux ----------------
__global__ void offsets_aux_kernel(float* __restrict__ out, int out_size){
    if (threadIdx.x == 0 && blockIdx.x == 0){
        int off = 0;
        float aux = 0.f;
        for (int e = 0; e < NEXP; e++){
            g_off[e] = off;
            off += g_cnt[e];
            aux += ((float)g_cnt[e] / (float)(T_TOK*2)) * (g_psum[e] / (float)T_TOK);
            g_fill[e] = 0;
        }
        g_off[NEXP] = off;
        if (out_size > T_TOK*DIM) out[T_TOK*DIM] = aux * (float)NEXP;
    }
}

// ---------------- scatter ----------------
__global__ void scatter_kernel(){
    int t = blockIdx.x * blockDim.x + threadIdx.x;
#pragma unroll
    for (int k = 0; k < 2; k++){
        int e = g_top[2*t+k];
        int pos = atomicAdd(&g_fill[e], 1);
        int slot = g_off[e] + pos;
        g_slot_tok[slot]  = t;
        g_slot_gate[slot] = g_w[2*t+k];
        g_tok_slot[2*t+k] = slot;
    }
}

// ---------------- grouped GEMM 1&3 + SwiGLU (cp.async 3-stage, fp16) -------
// 128 slot-rows x 128 F-cols; 512 threads; warp tile 32x32; K-tile 32.
__global__ __launch_bounds__(512) void gemm13_kernel(){
    const int e   = blockIdx.z;
    const int off = g_off[e];
    const int cnt = g_off[e+1] - off;
    const int m0  = blockIdx.x * 128;
    if (m0 >= cnt) return;
    const int n0  = blockIdx.y * 128;

    extern __shared__ __align__(16) uint32_t dynu[];
    __shared__ int sTok[128];

    const int tid = threadIdx.x;
    if (tid < 128){
        int m = m0 + tid; if (m >= cnt) m = cnt - 1;
        sTok[tid] = g_slot_tok[off + m];
    }
    __syncthreads();

    const uint32_t smBase = smem_u32(dynu);
    const int arow = tid & 127;
    const int aq   = tid >> 7;                  // 0..3
    const int kpi  = tid >> 5;                  // 0..15
    const int nseg = tid & 31;

    const uint32_t* aSrc  = g_xi  + (size_t)sTok[arow]*(DIM/2) + aq*4;
    const uint32_t* b1Src = g_w1i + ((size_t)e*(DIM/2) + kpi)*FDIM + n0 + nseg*4;
    const uint32_t* b3Src = g_w3i + ((size_t)e*(DIM/2) + kpi)*FDIM + n0 + nseg*4;
    const uint32_t aDst  = smBase + (uint32_t)(arow*ASTRW + aq*4)*4u;
    const uint32_t b1Dst = smBase + A_BYTES + (uint32_t)(kpi*BSTRW + nseg*4)*4u;
    const uint32_t b3Dst = smBase + A_BYTES + B_BYTES + (uint32_t)(kpi*BSTRW + nseg*4)*4u;

    auto ISSUE = [&](int kt, int s){
        uint32_t so = (uint32_t)s * ST13;
        cp16(aDst  + so, aSrc  + kt*16);
        cp16(b1Dst + so, b1Src + (size_t)kt*16*FDIM);
        cp16(b3Dst + so, b3Src + (size_t)kt*16*FDIM);
        cp_commit();
    };

    float acc1[2][4][4], acc3[2][4][4];
#pragma unroll
    for (int i = 0; i < 2; i++)
#pragma unroll
        for (int j = 0; j < 4; j++)
#pragma unroll
            for (int k = 0; k < 4; k++){ acc1[i][j][k] = 0.f; acc3[i][j][k] = 0.f; }

    const int lane = tid & 31, wid = tid >> 5;
    const int wm = (wid & 3) * 32, wn = (wid >> 2) * 32;
    const int g = lane >> 2, tg = lane & 3;

    auto COMPUTE = [&](int s){
        const uint32_t* a  = dynu + (size_t)s*(ST13/4);
        const uint32_t* b1 = a + A_BYTES/4;
        const uint32_t* b3 = b1 + B_BYTES/4;
#pragma unroll
        for (int ks = 0; ks < 2; ks++){
            const int kp0 = ks * 8;
            uint32_t af[2][4];
#pragma unroll
            for (int mi = 0; mi < 2; mi++){
                int r0 = wm + mi * 16;
                af[mi][0] = a[(r0+g  )*ASTRW + kp0+tg  ];
                af[mi][1] = a[(r0+8+g)*ASTRW + kp0+tg  ];
                af[mi][2] = a[(r0+g  )*ASTRW + kp0+4+tg];
                af[mi][3] = a[(r0+8+g)*ASTRW + kp0+4+tg];
            }
#pragma unroll
            for (int ni = 0; ni < 4; ni++){
                int nb = wn + ni * 8;
                uint32_t b1f[2] = { b1[(kp0+tg)*BSTRW + nb+g], b1[(kp0+4+tg)*BSTRW + nb+g] };
                uint32_t b3f[2] = { b3[(kp0+tg)*BSTRW + nb+g], b3[(kp0+4+tg)*BSTRW + nb+g] };
#pragma unroll
                for (int mi = 0; mi < 2; mi++){
                    mma16(acc1[mi][ni], af[mi], b1f);
                    mma16(acc3[mi][ni], af[mi], b3f);
                }
            }
        }
    };

    const int NK = DIM / 32;                    // 32
    ISSUE(0, 0); ISSUE(1, 1);
    int buf = 0;
    for (int kt = 0; kt < NK; kt++){
        if (kt == NK-1) cp_wait0(); else cp_wait1();
        __syncthreads();
        if (kt + 2 < NK){
            int nb = buf + 2; if (nb >= 3) nb -= 3;
            ISSUE(kt + 2, nb);
        }
        COMPUTE(buf);
        if (++buf == 3) buf = 0;
    }

    // epilogue: h = silu(a1)*a3 -> g_Hu (fp16 pairs along f)
#pragma unroll
    for (int mi = 0; mi < 2; mi++){
#pragma unroll
        for (int ni = 0; ni < 4; ni++){
            int col = n0 + wn + ni * 8 + tg * 2;
#pragma unroll
            for (int h = 0; h < 2; h++){
                int r = wm + mi * 16 + g + h * 8;
                int m = m0 + r;
                if (m < cnt){
                    float v1a = acc1[mi][ni][h*2], v1b = acc1[mi][ni][h*2+1];
                    float v3a = acc3[mi][ni][h*2], v3b = acc3[mi][ni][h*2+1];
                    float ox = (v1a / (1.f + __expf(-v1a))) * v3a;
                    float oy = (v1b / (1.f + __expf(-v1b))) * v3b;
                    g_Hu[(size_t)(off + m)*(FDIM/2) + (col >> 1)] = pack_h2(ox, oy);
                }
            }
        }
    }
}

// ---------------- grouped GEMM 2 (H @ W2) + gate (cp.async 3-stage) --------
__global__ __launch_bounds__(512) void gemm2_kernel(){
    const int e   = blockIdx.z;
    const int off = g_off[e];
    const int cnt = g_off[e+1] - off;
    const int m0  = blockIdx.x * 128;
    if (m0 >= cnt) return;
    const int n0  = blockIdx.y * 128;

    extern __shared__ __align__(16) uint32_t dynu[];

    const int tid = threadIdx.x;
    const uint32_t smBase = smem_u32(dynu);
    const int arow = tid & 127;
    const int aq   = tid >> 7;
    const int kpi  = tid >> 5;
    const int nseg = tid & 31;

    int mrow = m0 + arow; if (mrow >= cnt) mrow = cnt - 1;
    const uint32_t* aSrc = g_Hu  + (size_t)(off + mrow)*(FDIM/2) + aq*4;
    const uint32_t* bSrc = g_w2i + ((size_t)e*(FDIM/2) + kpi)*DIM + n0 + nseg*4;
    const uint32_t aDst = smBase + (uint32_t)(arow*ASTRW + aq*4)*4u;
    const uint32_t bDst = smBase + A_BYTES + (uint32_t)(kpi*BSTRW + nseg*4)*4u;

    auto ISSUE = [&](int kt, int s){
        uint32_t so = (uint32_t)s * ST2;
        cp16(aDst + so, aSrc + kt*16);
        cp16(bDst + so, bSrc + (size_t)kt*16*DIM);
        cp_commit();
    };

    float acc[2][4][4];
#pragma unroll
    for (int i = 0; i < 2; i++)
#pragma unroll
        for (int j = 0; j < 4; j++)
#pragma unroll
            for (int k = 0; k < 4; k++) acc[i][j][k] = 0.f;

    const int lane = tid & 31, wid = tid >> 5;
    const int wm = (wid & 3) * 32, wn = (wid >> 2) * 32;
    const int g = lane >> 2, tg = lane & 3;

    auto COMPUTE = [&](int s){
        const uint32_t* a = dynu + (size_t)s*(ST2/4);
        const uint32_t* b = a + A_BYTES/4;
#pragma unroll
        for (int ks = 0; ks < 2; ks++){
            const int kp0 = ks * 8;
            uint32_t af[2][4];
#pragma unroll
            for (int mi = 0; mi < 2; mi++){
                int r0 = wm + mi * 16;
                af[mi][0] = a[(r0+g  )*ASTRW + kp0+tg  ];
                af[mi][1] = a[(r0+8+g)*ASTRW + kp0+tg  ];
                af[mi][2] = a[(r0+g  )*ASTRW + kp0+4+tg];
                af[mi][3] = a[(r0+8+g)*ASTRW + kp0+4+tg];
            }
#pragma unroll
            for (int ni = 0; ni < 4; ni++){
                int nb = wn + ni * 8;
                uint32_t bf[2] = { b[(kp0+tg)*BSTRW + nb+g], b[(kp0+4+tg)*BSTRW + nb+g] };
#pragma unroll
                for (int mi = 0; mi < 2; mi++)
                    mma16(acc[mi][ni], af[mi], bf);
            }
        }
    };

    const int NK = FDIM / 32;                   // 128
    ISSUE(0, 0); ISSUE(1, 1);
    int buf = 0;
    for (int kt = 0; kt < NK; kt++){
        if (kt == NK-1) cp_wait0(); else cp_wait1();
        __syncthreads();
        if (kt + 2 < NK){
            int nb = buf + 2; if (nb >= 3) nb -= 3;
            ISSUE(kt + 2, nb);
        }
        COMPUTE(buf);
        if (++buf == 3) buf = 0;
    }

#pragma unroll
    for (int mi = 0; mi < 2; mi++){
#pragma unroll
        for (int h = 0; h < 2; h++){
            int r = wm + mi * 16 + g + h * 8;
            int m = m0 + r;
            if (m < cnt){
                float gate = g_slot_gate[off + m];
#pragma unroll
                for (int ni = 0; ni < 4; ni++){
                    int col = n0 + wn + ni * 8 + tg * 2;
                    float2 o;
                    o.x = acc[mi][ni][h*2]   * gate;
                    o.y = acc[mi][ni][h*2+1] * gate;
                    *(float2*)&g_Y[(size_t)(off + m) * DIM + col] = o;
                }
            }
        }
    }
}

// ---------------- combine ----------------
__global__ void combine_kernel(float* __restrict__ out){
    int i = blockIdx.x * blockDim.x + threadIdx.x;
    int t = i >> 8;
    int rem = i & 255;
    int s0 = g_tok_slot[2*t], s1 = g_tok_slot[2*t+1];
    const float4* Y = (const float4*)g_Y;
    float4 a = Y[(size_t)s0 * 256 + rem];
    float4 b = Y[(size_t)s1 * 256 + rem];
    ((float4*)out)[i] = make_float4(a.x + b.x, a.y + b.y, a.z + b.z, a.w + b.w);
}

// ---------------- launch ----------------
extern "C" void kernel_launch(void* const* d_in, const int* in_sizes, int n_in,
                              void* d_out, int out_size){
    const float* x  = (const float*)d_in[0];
    const float* Wg = (const float*)d_in[1];
    const float* bg = (const float*)d_in[2];
    const float* W1 = (const float*)d_in[3];
    const float* W3 = (const float*)d_in[4];
    const float* W2 = (const float*)d_in[5];
    float* out = (float*)d_out;

    const int dyn13 = 3 * ST13;   // 82944 B
    const int dyn2  = 3 * ST2;    // 56832 B
    cudaFuncSetAttribute(gemm13_kernel, cudaFuncAttributeMaxDynamicSharedMemorySize, dyn13);
    cudaFuncSetAttribute(gemm2_kernel,  cudaFuncAttributeMaxDynamicSharedMemorySize, dyn2);

    init_kernel<<<1, 32>>>();
    cvt_x_kernel  <<<(T_TOK*(DIM/2))/256, 256>>>(x);
    cvt_w13_kernel<<<(NEXP*(DIM/2)*FDIM)/256, 256>>>(W1, W3);
    cvt_w2_kernel <<<(NEXP*(FDIM/2)*DIM)/256, 256>>>(W2);
    router_kernel<<<T_TOK/8, 256>>>(x, Wg, bg);
    offsets_aux_kernel<<<1, 1>>>(out, out_size);
    scatter_kernel<<<T_TOK/256, 256>>>();
    gemm13_kernel<<<dim3(SLOTS/128, FDIM/128, NEXP), 512, dyn13>>>();
    gemm2_kernel <<<dim3(SLOTS/128, DIM/128,  NEXP), 512, dyn2 >>>();
    combine_kernel<<<(T_TOK*DIM/4)/256, 256>>>(out);
}